// round 14
// baseline (speedup 1.0000x reference)
#include <cuda_runtime.h>

#define NTOK  4096
#define HEADS 16
#define HDIM  64
#define EMBED 1024

// ---------------- device scratch (static, allowed) ----------------
__device__ float g_Q[NTOK * EMBED];    // [n][h][64] tf32-rounded
__device__ float g_K[NTOK * EMBED];
__device__ float g_V[NTOK * EMBED];
__device__ float g_ctx[NTOK * EMBED];  // [n][h*64+d] tf32-rounded
__device__ float g_inv[HEADS * NTOK];  // 1 / sum_k exp(S/32)

// ---------------- helpers ----------------
__device__ __forceinline__ float to_tf32(float x) {
    unsigned u;
    asm("cvt.rna.tf32.f32 %0, %1;" : "=r"(u) : "f"(x));
    return __uint_as_float(u);
}

__device__ __forceinline__ void mma8(float (&d)[4], const unsigned (&a)[4],
                                     unsigned b0, unsigned b1) {
    asm("mma.sync.aligned.m16n8k8.row.col.f32.tf32.tf32.f32 "
        "{%0,%1,%2,%3}, {%4,%5,%6,%7}, {%8,%9}, {%0,%1,%2,%3};"
        : "+f"(d[0]), "+f"(d[1]), "+f"(d[2]), "+f"(d[3])
        : "r"(a[0]), "r"(a[1]), "r"(a[2]), "r"(a[3]), "r"(b0), "r"(b1));
}

// A[128 x 64] (stride 68) row-major, B[n][k] layout (stride 68, n rows of 64 k),
// contraction over 64.  Warp computes rows [rowA, rowA+32), cols [colB, colB+8*NI).
template <int NI>
__device__ __forceinline__ void mma_tile68(const float* __restrict__ A,
                                           const float* __restrict__ B,
                                           float (&acc)[2][NI][4],
                                           int rowA, int colB, int g, int t) {
#pragma unroll
    for (int ks = 0; ks < 8; ++ks) {
        unsigned a[2][4];
#pragma unroll
        for (int mi = 0; mi < 2; ++mi) {
            const float* ap = A + (rowA + mi * 16 + g) * 68 + ks * 8 + t;
            a[mi][0] = __float_as_uint(ap[0]);
            a[mi][1] = __float_as_uint(ap[8 * 68]);
            a[mi][2] = __float_as_uint(ap[4]);
            a[mi][3] = __float_as_uint(ap[8 * 68 + 4]);
        }
#pragma unroll
        for (int ni = 0; ni < NI; ++ni) {
            const float* bp = B + (colB + ni * 8 + g) * 68 + ks * 8 + t;
            unsigned b0 = __float_as_uint(bp[0]);
            unsigned b1 = __float_as_uint(bp[4]);
            mma8(acc[0][ni], a[0], b0, b1);
            mma8(acc[1][ni], a[1], b0, b1);
        }
    }
}

// ---------------- kernel 1: QKV projection ----------------
// X = pairs viewed [65536 x 64] (row m = n*16 + h).  Out = X @ W^T for Wq/Wk/Wv.
__global__ void __launch_bounds__(256, 1)
qkv_kernel(const float* __restrict__ pairs, const float* __restrict__ Wq,
           const float* __restrict__ Wk, const float* __restrict__ Wv) {
    extern __shared__ float sm[];
    float* Xs = sm;                 // 128 x 68
    float* Ws = sm + 128 * 68;      // 3 x 64 x 68  (Ws[e][d])

    const int tid = threadIdx.x;
    const int lane = tid & 31, wid = tid >> 5;
    const int g = lane >> 2, t = lane & 3;
    const int rowb = (wid >> 1) * 32;
    const int colb = (wid & 1) * 32;
    const int m0 = blockIdx.x * 128;

    for (int i = tid; i < 128 * 16; i += 256) {
        int r = i >> 4, c4 = i & 15;
        float4 v = *(const float4*)(pairs + (size_t)(m0 + r) * 64 + c4 * 4);
        v.x = to_tf32(v.x); v.y = to_tf32(v.y); v.z = to_tf32(v.z); v.w = to_tf32(v.w);
        *(float4*)&Xs[r * 68 + c4 * 4] = v;
    }
    for (int i = tid; i < 3 * 64 * 16; i += 256) {
        int mat = i >> 10, rem = i & 1023;
        int r = rem >> 4, c4 = rem & 15;
        const float* src = (mat == 0) ? Wq : (mat == 1) ? Wk : Wv;
        float4 v = *(const float4*)(src + r * 64 + c4 * 4);
        v.x = to_tf32(v.x); v.y = to_tf32(v.y); v.z = to_tf32(v.z); v.w = to_tf32(v.w);
        *(float4*)&Ws[mat * (64 * 68) + r * 68 + c4 * 4] = v;
    }
    __syncthreads();

#pragma unroll
    for (int mat = 0; mat < 3; ++mat) {
        float acc[2][4][4] = {};
        mma_tile68<4>(Xs, Ws + mat * (64 * 68), acc, rowb, colb, g, t);
        float* dst = (mat == 0) ? g_Q : (mat == 1) ? g_K : g_V;
#pragma unroll
        for (int mi = 0; mi < 2; ++mi)
#pragma unroll
            for (int ni = 0; ni < 4; ++ni) {
                int r = rowb + mi * 16 + g;
                int c = colb + ni * 8 + 2 * t;
                size_t base = (size_t)(m0 + r) * 64 + c;
                dst[base]              = to_tf32(acc[mi][ni][0]);
                dst[base + 1]          = to_tf32(acc[mi][ni][1]);
                dst[base + 8 * 64]     = to_tf32(acc[mi][ni][2]);
                dst[base + 8 * 64 + 1] = to_tf32(acc[mi][ni][3]);
            }
    }
}

// ---------------- kernel 2a: energy = Q K^T, rowsums -> g_inv ----------------
// grid (32 q-tiles, 16 heads), 256 threads, 2 CTAs/SM.
// Energy stored straight from MMA accumulators (coalesced float2), exp rowsums
// kept in per-thread registers across all k-tiles (fragment rows are kt-invariant).
__global__ void __launch_bounds__(256, 2)
energy_kernel(float* __restrict__ energy) {
    extern __shared__ float sm[];
    float* Qs = sm;                 // 128 x 68
    float* Ks = Qs + 128 * 68;      // 128 x 68
    float* red = Ks + 128 * 68;     // 256

    const int tid = threadIdx.x;
    const int lane = tid & 31, wid = tid >> 5;
    const int g = lane >> 2, t = lane & 3;
    const int rowb = (wid >> 1) * 32;
    const int wn = wid & 1;
    const int q0 = blockIdx.x * 128;
    const int h = blockIdx.y;
    const float kScale = 0.03125f;  // 1/sqrt(1024)

    for (int i = tid; i < 128 * 16; i += 256) {
        int r = i >> 4, c4 = i & 15;
        *(float4*)&Qs[r * 68 + c4 * 4] =
            *(const float4*)(g_Q + (size_t)(q0 + r) * EMBED + h * 64 + c4 * 4);
    }

    float rowacc[4] = {0.f, 0.f, 0.f, 0.f};   // rows rowb + {g, g+8, 16+g, 24+g}
    float* edst = energy + ((size_t)h * NTOK + q0) * NTOK;

    for (int kt = 0; kt < 32; ++kt) {
        const int k0 = kt * 128;
        __syncthreads();            // prior MMA done reading Ks (also covers Q stage)
        for (int i = tid; i < 128 * 16; i += 256) {
            int r = i >> 4, c4 = i & 15;
            *(float4*)&Ks[r * 68 + c4 * 4] =
                *(const float4*)(g_K + (size_t)(k0 + r) * EMBED + h * 64 + c4 * 4);
        }
        __syncthreads();

        float sacc[2][8][4] = {};
        mma_tile68<8>(Qs, Ks, sacc, rowb, wn * 64, g, t);

#pragma unroll
        for (int mi = 0; mi < 2; ++mi) {
            int r = rowb + mi * 16 + g;
#pragma unroll
            for (int ni = 0; ni < 8; ++ni) {
                int c = k0 + wn * 64 + ni * 8 + 2 * t;
                *(float2*)(edst + (size_t)r * NTOK + c) =
                    make_float2(sacc[mi][ni][0], sacc[mi][ni][1]);
                *(float2*)(edst + (size_t)(r + 8) * NTOK + c) =
                    make_float2(sacc[mi][ni][2], sacc[mi][ni][3]);
                rowacc[mi * 2]     += __expf(sacc[mi][ni][0] * kScale)
                                    + __expf(sacc[mi][ni][1] * kScale);
                rowacc[mi * 2 + 1] += __expf(sacc[mi][ni][2] * kScale)
                                    + __expf(sacc[mi][ni][3] * kScale);
            }
        }
    }

    // reduce over t within each quad, then across the two wn warps via smem
#pragma unroll
    for (int j = 0; j < 4; ++j) {
        float s = rowacc[j];
        s += __shfl_xor_sync(0xffffffffu, s, 1);
        s += __shfl_xor_sync(0xffffffffu, s, 2);
        rowacc[j] = s;
    }
    if (t == 0) {
        red[wn * 128 + rowb + g]      = rowacc[0];
        red[wn * 128 + rowb + g + 8]  = rowacc[1];
        red[wn * 128 + rowb + 16 + g] = rowacc[2];
        red[wn * 128 + rowb + 24 + g] = rowacc[3];
    }
    __syncthreads();
    if (tid < 128)
        g_inv[h * NTOK + q0 + tid] = 1.0f / (red[tid] + red[128 + tid]);
}

// ---------------- kernel 2b: att = softmax(energy), ctx = att @ V ----------------
// grid (32 q-tiles, 16 heads), 256 threads, 2 CTAs/SM.
// Reads energy back coalesced (no QK^T recompute), writes att directly, stages
// tf32-rounded P in smem only for MMA fragment re-layout.
__global__ void __launch_bounds__(256, 2)
attctx_kernel(const float* __restrict__ energy, float* __restrict__ att) {
    extern __shared__ float sm[];
    float* Vs = sm;                 // 128 x 72
    float* Ps = Vs + 128 * 72;      // 128 x 132
    float* inv_s = Ps + 128 * 132;  // 128

    const int tid = threadIdx.x;
    const int lane = tid & 31, wid = tid >> 5;
    const int g = lane >> 2, t = lane & 3;
    const int rowb = (wid >> 1) * 32;
    const int wn = wid & 1;
    const int q0 = blockIdx.x * 128;
    const int h = blockIdx.y;
    const float kScale = 0.03125f;

    if (tid < 128) inv_s[tid] = g_inv[h * NTOK + q0 + tid];

    const float* esrc = energy + ((size_t)h * NTOK + q0) * NTOK;
    float* adst = att + ((size_t)h * NTOK + q0) * NTOK;

    float cacc[2][4][4] = {};
    for (int kt = 0; kt < 32; ++kt) {
        const int k0 = kt * 128;
        __syncthreads();            // prior MMA done reading Vs/Ps (also inv_s ready)

        // stage V tile
        for (int i = tid; i < 128 * 16; i += 256) {
            int r = i >> 4, c4 = i & 15;
            *(float4*)&Vs[r * 72 + c4 * 4] =
                *(const float4*)(g_V + (size_t)(k0 + r) * EMBED + h * 64 + c4 * 4);
        }
        // energy -> P: write att (fp32) and Ps (tf32) — all coalesced
        for (int i = tid; i < 128 * 32; i += 256) {
            int r = i >> 5, c4 = i & 31;
            float4 e = *(const float4*)(esrc + (size_t)r * NTOK + k0 + c4 * 4);
            float iv = inv_s[r];
            float4 p;
            p.x = __expf(e.x * kScale) * iv;
            p.y = __expf(e.y * kScale) * iv;
            p.z = __expf(e.z * kScale) * iv;
            p.w = __expf(e.w * kScale) * iv;
            *(float4*)(adst + (size_t)r * NTOK + k0 + c4 * 4) = p;
            p.x = to_tf32(p.x); p.y = to_tf32(p.y);
            p.z = to_tf32(p.z); p.w = to_tf32(p.w);
            *(float4*)&Ps[r * 132 + c4 * 4] = p;
        }
        __syncthreads();

        // ctx += P(128x128) @ V(128x64); warp: rows [rowb,rowb+32) x d [wn*32,+32)
#pragma unroll
        for (int ks = 0; ks < 16; ++ks) {
            unsigned a[2][4];
#pragma unroll
            for (int mi = 0; mi < 2; ++mi) {
                const float* pp = Ps + (rowb + mi * 16 + g) * 132 + ks * 8 + t;
                a[mi][0] = __float_as_uint(pp[0]);
                a[mi][1] = __float_as_uint(pp[8 * 132]);
                a[mi][2] = __float_as_uint(pp[4]);
                a[mi][3] = __float_as_uint(pp[8 * 132 + 4]);
            }
#pragma unroll
            for (int ni = 0; ni < 4; ++ni) {
                const float* vp = Vs + (ks * 8 + t) * 72 + wn * 32 + ni * 8 + g;
                unsigned b0 = __float_as_uint(vp[0]);
                unsigned b1 = __float_as_uint(vp[4 * 72]);
                mma8(cacc[0][ni], a[0], b0, b1);
                mma8(cacc[1][ni], a[1], b0, b1);
            }
        }
    }

#pragma unroll
    for (int mi = 0; mi < 2; ++mi)
#pragma unroll
        for (int ni = 0; ni < 4; ++ni) {
            int r = rowb + mi * 16 + g;
            int c = wn * 32 + ni * 8 + 2 * t;
            size_t base = (size_t)(q0 + r) * EMBED + h * 64 + c;
            g_ctx[base]                 = to_tf32(cacc[mi][ni][0]);
            g_ctx[base + 1]             = to_tf32(cacc[mi][ni][1]);
            g_ctx[base + 8 * EMBED]     = to_tf32(cacc[mi][ni][2]);
            g_ctx[base + 8 * EMBED + 1] = to_tf32(cacc[mi][ni][3]);
        }
}

// ---------------- kernel 3: out = ctx @ Wo^T + bo ----------------
__global__ void __launch_bounds__(256, 1)
outproj_kernel(const float* __restrict__ Wo, const float* __restrict__ bo,
               float* __restrict__ out) {
    extern __shared__ float sm[];
    float* As = sm;                // 128 x 68
    float* Bs = As + 128 * 68;     // 128 x 68  (Bs[e][c])
    float* bs = Bs + 128 * 68;     // 128

    const int tid = threadIdx.x;
    const int lane = tid & 31, wid = tid >> 5;
    const int g = lane >> 2, t = lane & 3;
    const int rowb = (wid >> 1) * 32;
    const int wn = wid & 1;
    const int n0 = blockIdx.x * 128;
    const int m0 = blockIdx.y * 128;

    if (tid < 128) bs[tid] = bo[n0 + tid];

    float acc[2][8][4] = {};
    for (int ch = 0; ch < 16; ++ch) {
        const int c0 = ch * 64;
        __syncthreads();
        for (int i = tid; i < 128 * 16; i += 256) {
            int r = i >> 4, c4 = i & 15;
            *(float4*)&As[r * 68 + c4 * 4] =
                *(const float4*)(g_ctx + (size_t)(m0 + r) * EMBED + c0 + c4 * 4);
            float4 w = *(const float4*)(Wo + (size_t)(n0 + r) * EMBED + c0 + c4 * 4);
            w.x = to_tf32(w.x); w.y = to_tf32(w.y); w.z = to_tf32(w.z); w.w = to_tf32(w.w);
            *(float4*)&Bs[r * 68 + c4 * 4] = w;
        }
        __syncthreads();
        mma_tile68<8>(As, Bs, acc, rowb, wn * 64, g, t);
    }

#pragma unroll
    for (int mi = 0; mi < 2; ++mi)
#pragma unroll
        for (int ni = 0; ni < 8; ++ni) {
            int r = rowb + mi * 16 + g;
            int c = wn * 64 + ni * 8 + 2 * t;
            size_t base = (size_t)(m0 + r) * EMBED + n0 + c;
            out[base]                 = acc[mi][ni][0] + bs[c];
            out[base + 1]             = acc[mi][ni][1] + bs[c + 1];
            out[base + 8 * EMBED]     = acc[mi][ni][2] + bs[c];
            out[base + 8 * EMBED + 1] = acc[mi][ni][3] + bs[c + 1];
        }
}

// ---------------- launch ----------------
extern "C" void kernel_launch(void* const* d_in, const int* in_sizes, int n_in,
                              void* d_out, int out_size) {
    const float* pairs = (const float*)d_in[0];
    const float* Wq    = (const float*)d_in[1];
    const float* Wk    = (const float*)d_in[2];
    const float* Wv    = (const float*)d_in[3];
    const float* Wo    = (const float*)d_in[4];
    const float* bo    = (const float*)d_in[5];

    float* out    = (float*)d_out;
    float* energy = out + (size_t)NTOK * EMBED;
    float* att    = energy + (size_t)HEADS * NTOK * NTOK;

    const int smem1 = (128 * 68 + 3 * 64 * 68) * 4;              // 87,040
    const int smemE = (128 * 68 * 2 + 256) * 4;                  // 70,656
    const int smemP = (128 * 72 + 128 * 132 + 128) * 4;          // 104,960
    const int smem3 = (128 * 68 * 2 + 128) * 4;                  // 70,144

    cudaFuncSetAttribute(qkv_kernel,     cudaFuncAttributeMaxDynamicSharedMemorySize, smem1);
    cudaFuncSetAttribute(energy_kernel,  cudaFuncAttributeMaxDynamicSharedMemorySize, smemE);
    cudaFuncSetAttribute(attctx_kernel,  cudaFuncAttributeMaxDynamicSharedMemorySize, smemP);
    cudaFuncSetAttribute(outproj_kernel, cudaFuncAttributeMaxDynamicSharedMemorySize, smem3);

    qkv_kernel<<<512, 256, smem1>>>(pairs, Wq, Wk, Wv);
    energy_kernel<<<dim3(32, 16), 256, smemE>>>(energy);
    attctx_kernel<<<dim3(32, 16), 256, smemP>>>(energy, att);
    outproj_kernel<<<dim3(8, 32), 256, smem3>>>(Wo, bo, out);
}

// round 15
// speedup vs baseline: 1.0104x; 1.0104x over previous
#include <cuda_runtime.h>

#define NTOK  4096
#define HEADS 16
#define HDIM  64
#define EMBED 1024

// ---------------- device scratch (static, allowed) ----------------
__device__ float g_Q[NTOK * EMBED];    // [n][h][64] tf32-rounded
__device__ float g_K[NTOK * EMBED];
__device__ float g_V[NTOK * EMBED];
__device__ float g_ctx[NTOK * EMBED];  // [n][h*64+d] tf32-rounded
__device__ float g_inv[HEADS * NTOK];  // 1 / sum_k exp(S/32)

// ---------------- helpers ----------------
__device__ __forceinline__ float to_tf32(float x) {
    unsigned u;
    asm("cvt.rna.tf32.f32 %0, %1;" : "=r"(u) : "f"(x));
    return __uint_as_float(u);
}

__device__ __forceinline__ void mma8(float (&d)[4], const unsigned (&a)[4],
                                     unsigned b0, unsigned b1) {
    asm("mma.sync.aligned.m16n8k8.row.col.f32.tf32.tf32.f32 "
        "{%0,%1,%2,%3}, {%4,%5,%6,%7}, {%8,%9}, {%0,%1,%2,%3};"
        : "+f"(d[0]), "+f"(d[1]), "+f"(d[2]), "+f"(d[3])
        : "r"(a[0]), "r"(a[1]), "r"(a[2]), "r"(a[3]), "r"(b0), "r"(b1));
}

// A[128 x 64] (stride 68) row-major, B[n][k] layout (stride 68, n rows of 64 k),
// contraction over 64.  Warp computes rows [rowA, rowA+32), cols [colB, colB+8*NI).
template <int NI>
__device__ __forceinline__ void mma_tile68(const float* __restrict__ A,
                                           const float* __restrict__ B,
                                           float (&acc)[2][NI][4],
                                           int rowA, int colB, int g, int t) {
#pragma unroll
    for (int ks = 0; ks < 8; ++ks) {
        unsigned a[2][4];
#pragma unroll
        for (int mi = 0; mi < 2; ++mi) {
            const float* ap = A + (rowA + mi * 16 + g) * 68 + ks * 8 + t;
            a[mi][0] = __float_as_uint(ap[0]);
            a[mi][1] = __float_as_uint(ap[8 * 68]);
            a[mi][2] = __float_as_uint(ap[4]);
            a[mi][3] = __float_as_uint(ap[8 * 68 + 4]);
        }
#pragma unroll
        for (int ni = 0; ni < NI; ++ni) {
            const float* bp = B + (colB + ni * 8 + g) * 68 + ks * 8 + t;
            unsigned b0 = __float_as_uint(bp[0]);
            unsigned b1 = __float_as_uint(bp[4]);
            mma8(acc[0][ni], a[0], b0, b1);
            mma8(acc[1][ni], a[1], b0, b1);
        }
    }
}

// ---------------- kernel 1: QKV projection ----------------
// X = pairs viewed [65536 x 64] (row m = n*16 + h).  Out = X @ W^T for Wq/Wk/Wv.
__global__ void __launch_bounds__(256, 1)
qkv_kernel(const float* __restrict__ pairs, const float* __restrict__ Wq,
           const float* __restrict__ Wk, const float* __restrict__ Wv) {
    extern __shared__ float sm[];
    float* Xs = sm;                 // 128 x 68
    float* Ws = sm + 128 * 68;      // 3 x 64 x 68  (Ws[e][d])

    const int tid = threadIdx.x;
    const int lane = tid & 31, wid = tid >> 5;
    const int g = lane >> 2, t = lane & 3;
    const int rowb = (wid >> 1) * 32;
    const int colb = (wid & 1) * 32;
    const int m0 = blockIdx.x * 128;

    for (int i = tid; i < 128 * 16; i += 256) {
        int r = i >> 4, c4 = i & 15;
        float4 v = *(const float4*)(pairs + (size_t)(m0 + r) * 64 + c4 * 4);
        v.x = to_tf32(v.x); v.y = to_tf32(v.y); v.z = to_tf32(v.z); v.w = to_tf32(v.w);
        *(float4*)&Xs[r * 68 + c4 * 4] = v;
    }
    for (int i = tid; i < 3 * 64 * 16; i += 256) {
        int mat = i >> 10, rem = i & 1023;
        int r = rem >> 4, c4 = rem & 15;
        const float* src = (mat == 0) ? Wq : (mat == 1) ? Wk : Wv;
        float4 v = *(const float4*)(src + r * 64 + c4 * 4);
        v.x = to_tf32(v.x); v.y = to_tf32(v.y); v.z = to_tf32(v.z); v.w = to_tf32(v.w);
        *(float4*)&Ws[mat * (64 * 68) + r * 68 + c4 * 4] = v;
    }
    __syncthreads();

#pragma unroll
    for (int mat = 0; mat < 3; ++mat) {
        float acc[2][4][4] = {};
        mma_tile68<4>(Xs, Ws + mat * (64 * 68), acc, rowb, colb, g, t);
        float* dst = (mat == 0) ? g_Q : (mat == 1) ? g_K : g_V;
#pragma unroll
        for (int mi = 0; mi < 2; ++mi)
#pragma unroll
            for (int ni = 0; ni < 4; ++ni) {
                int r = rowb + mi * 16 + g;
                int c = colb + ni * 8 + 2 * t;
                size_t base = (size_t)(m0 + r) * 64 + c;
                dst[base]              = to_tf32(acc[mi][ni][0]);
                dst[base + 1]          = to_tf32(acc[mi][ni][1]);
                dst[base + 8 * 64]     = to_tf32(acc[mi][ni][2]);
                dst[base + 8 * 64 + 1] = to_tf32(acc[mi][ni][3]);
            }
    }
}

// ---------------- kernel 2a: energy = Q K^T, rowsums -> g_inv ----------------
// grid (32 q-tiles, 16 heads), 256 threads, 2 CTAs/SM.
// Energy stored straight from MMA accumulators (coalesced float2), exp rowsums
// kept in per-thread registers across all k-tiles (fragment rows are kt-invariant).
__global__ void __launch_bounds__(256, 2)
energy_kernel(float* __restrict__ energy) {
    extern __shared__ float sm[];
    float* Qs = sm;                 // 128 x 68
    float* Ks = Qs + 128 * 68;      // 128 x 68
    float* red = Ks + 128 * 68;     // 256

    const int tid = threadIdx.x;
    const int lane = tid & 31, wid = tid >> 5;
    const int g = lane >> 2, t = lane & 3;
    const int rowb = (wid >> 1) * 32;
    const int wn = wid & 1;
    const int q0 = blockIdx.x * 128;
    const int h = blockIdx.y;
    const float kScale = 0.03125f;  // 1/sqrt(1024)

    for (int i = tid; i < 128 * 16; i += 256) {
        int r = i >> 4, c4 = i & 15;
        *(float4*)&Qs[r * 68 + c4 * 4] =
            *(const float4*)(g_Q + (size_t)(q0 + r) * EMBED + h * 64 + c4 * 4);
    }

    float rowacc[4] = {0.f, 0.f, 0.f, 0.f};   // rows rowb + {g, g+8, 16+g, 24+g}
    float* edst = energy + ((size_t)h * NTOK + q0) * NTOK;

    for (int kt = 0; kt < 32; ++kt) {
        const int k0 = kt * 128;
        __syncthreads();            // prior MMA done reading Ks (also covers Q stage)
        for (int i = tid; i < 128 * 16; i += 256) {
            int r = i >> 4, c4 = i & 15;
            *(float4*)&Ks[r * 68 + c4 * 4] =
                *(const float4*)(g_K + (size_t)(k0 + r) * EMBED + h * 64 + c4 * 4);
        }
        __syncthreads();

        float sacc[2][8][4] = {};
        mma_tile68<8>(Qs, Ks, sacc, rowb, wn * 64, g, t);

#pragma unroll
        for (int mi = 0; mi < 2; ++mi) {
            int r = rowb + mi * 16 + g;
#pragma unroll
            for (int ni = 0; ni < 8; ++ni) {
                int c = k0 + wn * 64 + ni * 8 + 2 * t;
                *(float2*)(edst + (size_t)r * NTOK + c) =
                    make_float2(sacc[mi][ni][0], sacc[mi][ni][1]);
                *(float2*)(edst + (size_t)(r + 8) * NTOK + c) =
                    make_float2(sacc[mi][ni][2], sacc[mi][ni][3]);
                rowacc[mi * 2]     += __expf(sacc[mi][ni][0] * kScale)
                                    + __expf(sacc[mi][ni][1] * kScale);
                rowacc[mi * 2 + 1] += __expf(sacc[mi][ni][2] * kScale)
                                    + __expf(sacc[mi][ni][3] * kScale);
            }
        }
    }

    // reduce over t within each quad, then across the two wn warps via smem
#pragma unroll
    for (int j = 0; j < 4; ++j) {
        float s = rowacc[j];
        s += __shfl_xor_sync(0xffffffffu, s, 1);
        s += __shfl_xor_sync(0xffffffffu, s, 2);
        rowacc[j] = s;
    }
    if (t == 0) {
        red[wn * 128 + rowb + g]      = rowacc[0];
        red[wn * 128 + rowb + g + 8]  = rowacc[1];
        red[wn * 128 + rowb + 16 + g] = rowacc[2];
        red[wn * 128 + rowb + 24 + g] = rowacc[3];
    }
    __syncthreads();
    if (tid < 128)
        g_inv[h * NTOK + q0 + tid] = 1.0f / (red[tid] + red[128 + tid]);
}

// ---------------- kernel 2b: att = softmax(energy), ctx = att @ V ----------------
// grid (32 q-tiles, 16 heads), 256 threads, 2 CTAs/SM.
// Reads energy back coalesced (no QK^T recompute), writes att directly, stages
// tf32-rounded P in smem only for MMA fragment re-layout.
__global__ void __launch_bounds__(256, 2)
attctx_kernel(const float* __restrict__ energy, float* __restrict__ att) {
    extern __shared__ float sm[];
    float* Vs = sm;                 // 128 x 72
    float* Ps = Vs + 128 * 72;      // 128 x 132
    float* inv_s = Ps + 128 * 132;  // 128

    const int tid = threadIdx.x;
    const int lane = tid & 31, wid = tid >> 5;
    const int g = lane >> 2, t = lane & 3;
    const int rowb = (wid >> 1) * 32;
    const int wn = wid & 1;
    const int q0 = blockIdx.x * 128;
    const int h = blockIdx.y;
    const float kScale = 0.03125f;

    if (tid < 128) inv_s[tid] = g_inv[h * NTOK + q0 + tid];

    const float* esrc = energy + ((size_t)h * NTOK + q0) * NTOK;
    float* adst = att + ((size_t)h * NTOK + q0) * NTOK;

    float cacc[2][4][4] = {};
    for (int kt = 0; kt < 32; ++kt) {
        const int k0 = kt * 128;
        __syncthreads();            // prior MMA done reading Vs/Ps (also inv_s ready)

        // stage V tile
        for (int i = tid; i < 128 * 16; i += 256) {
            int r = i >> 4, c4 = i & 15;
            *(float4*)&Vs[r * 72 + c4 * 4] =
                *(const float4*)(g_V + (size_t)(k0 + r) * EMBED + h * 64 + c4 * 4);
        }
        // energy -> P: write att (fp32) and Ps (tf32) — all coalesced
        for (int i = tid; i < 128 * 32; i += 256) {
            int r = i >> 5, c4 = i & 31;
            float4 e = *(const float4*)(esrc + (size_t)r * NTOK + k0 + c4 * 4);
            float iv = inv_s[r];
            float4 p;
            p.x = __expf(e.x * kScale) * iv;
            p.y = __expf(e.y * kScale) * iv;
            p.z = __expf(e.z * kScale) * iv;
            p.w = __expf(e.w * kScale) * iv;
            *(float4*)(adst + (size_t)r * NTOK + k0 + c4 * 4) = p;
            p.x = to_tf32(p.x); p.y = to_tf32(p.y);
            p.z = to_tf32(p.z); p.w = to_tf32(p.w);
            *(float4*)&Ps[r * 132 + c4 * 4] = p;
        }
        __syncthreads();

        // ctx += P(128x128) @ V(128x64); warp: rows [rowb,rowb+32) x d [wn*32,+32)
#pragma unroll
        for (int ks = 0; ks < 16; ++ks) {
            unsigned a[2][4];
#pragma unroll
            for (int mi = 0; mi < 2; ++mi) {
                const float* pp = Ps + (rowb + mi * 16 + g) * 132 + ks * 8 + t;
                a[mi][0] = __float_as_uint(pp[0]);
                a[mi][1] = __float_as_uint(pp[8 * 132]);
                a[mi][2] = __float_as_uint(pp[4]);
                a[mi][3] = __float_as_uint(pp[8 * 132 + 4]);
            }
#pragma unroll
            for (int ni = 0; ni < 4; ++ni) {
                const float* vp = Vs + (ks * 8 + t) * 72 + wn * 32 + ni * 8 + g;
                unsigned b0 = __float_as_uint(vp[0]);
                unsigned b1 = __float_as_uint(vp[4 * 72]);
                mma8(cacc[0][ni], a[0], b0, b1);
                mma8(cacc[1][ni], a[1], b0, b1);
            }
        }
    }

#pragma unroll
    for (int mi = 0; mi < 2; ++mi)
#pragma unroll
        for (int ni = 0; ni < 4; ++ni) {
            int r = rowb + mi * 16 + g;
            int c = wn * 32 + ni * 8 + 2 * t;
            size_t base = (size_t)(q0 + r) * EMBED + h * 64 + c;
            g_ctx[base]                 = to_tf32(cacc[mi][ni][0]);
            g_ctx[base + 1]             = to_tf32(cacc[mi][ni][1]);
            g_ctx[base + 8 * EMBED]     = to_tf32(cacc[mi][ni][2]);
            g_ctx[base + 8 * EMBED + 1] = to_tf32(cacc[mi][ni][3]);
        }
}

// ---------------- kernel 3: out = ctx @ Wo^T + bo ----------------
__global__ void __launch_bounds__(256, 1)
outproj_kernel(const float* __restrict__ Wo, const float* __restrict__ bo,
               float* __restrict__ out) {
    extern __shared__ float sm[];
    float* As = sm;                // 128 x 68
    float* Bs = As + 128 * 68;     // 128 x 68  (Bs[e][c])
    float* bs = Bs + 128 * 68;     // 128

    const int tid = threadIdx.x;
    const int lane = tid & 31, wid = tid >> 5;
    const int g = lane >> 2, t = lane & 3;
    const int rowb = (wid >> 1) * 32;
    const int wn = wid & 1;
    const int n0 = blockIdx.x * 128;
    const int m0 = blockIdx.y * 128;

    if (tid < 128) bs[tid] = bo[n0 + tid];

    float acc[2][8][4] = {};
    for (int ch = 0; ch < 16; ++ch) {
        const int c0 = ch * 64;
        __syncthreads();
        for (int i = tid; i < 128 * 16; i += 256) {
            int r = i >> 4, c4 = i & 15;
            *(float4*)&As[r * 68 + c4 * 4] =
                *(const float4*)(g_ctx + (size_t)(m0 + r) * EMBED + c0 + c4 * 4);
            float4 w = *(const float4*)(Wo + (size_t)(n0 + r) * EMBED + c0 + c4 * 4);
            w.x = to_tf32(w.x); w.y = to_tf32(w.y); w.z = to_tf32(w.z); w.w = to_tf32(w.w);
            *(float4*)&Bs[r * 68 + c4 * 4] = w;
        }
        __syncthreads();
        mma_tile68<8>(As, Bs, acc, rowb, wn * 64, g, t);
    }

#pragma unroll
    for (int mi = 0; mi < 2; ++mi)
#pragma unroll
        for (int ni = 0; ni < 8; ++ni) {
            int r = rowb + mi * 16 + g;
            int c = wn * 64 + ni * 8 + 2 * t;
            size_t base = (size_t)(m0 + r) * EMBED + n0 + c;
            out[base]                 = acc[mi][ni][0] + bs[c];
            out[base + 1]             = acc[mi][ni][1] + bs[c + 1];
            out[base + 8 * EMBED]     = acc[mi][ni][2] + bs[c];
            out[base + 8 * EMBED + 1] = acc[mi][ni][3] + bs[c + 1];
        }
}

// ---------------- launch ----------------
extern "C" void kernel_launch(void* const* d_in, const int* in_sizes, int n_in,
                              void* d_out, int out_size) {
    const float* pairs = (const float*)d_in[0];
    const float* Wq    = (const float*)d_in[1];
    const float* Wk    = (const float*)d_in[2];
    const float* Wv    = (const float*)d_in[3];
    const float* Wo    = (const float*)d_in[4];
    const float* bo    = (const float*)d_in[5];

    float* out    = (float*)d_out;
    float* energy = out + (size_t)NTOK * EMBED;
    float* att    = energy + (size_t)HEADS * NTOK * NTOK;

    const int smem1 = (128 * 68 + 3 * 64 * 68) * 4;              // 87,040
    const int smemE = (128 * 68 * 2 + 256) * 4;                  // 70,656
    const int smemP = (128 * 72 + 128 * 132 + 128) * 4;          // 104,960
    const int smem3 = (128 * 68 * 2 + 128) * 4;                  // 70,144

    cudaFuncSetAttribute(qkv_kernel,     cudaFuncAttributeMaxDynamicSharedMemorySize, smem1);
    cudaFuncSetAttribute(energy_kernel,  cudaFuncAttributeMaxDynamicSharedMemorySize, smemE);
    cudaFuncSetAttribute(attctx_kernel,  cudaFuncAttributeMaxDynamicSharedMemorySize, smemP);
    cudaFuncSetAttribute(outproj_kernel, cudaFuncAttributeMaxDynamicSharedMemorySize, smem3);

    qkv_kernel<<<512, 256, smem1>>>(pairs, Wq, Wk, Wv);
    energy_kernel<<<dim3(32, 16), 256, smemE>>>(energy);
    attctx_kernel<<<dim3(32, 16), 256, smemP>>>(energy, att);
    outproj_kernel<<<dim3(8, 32), 256, smem3>>>(Wo, bo, out);
}